// round 7
// baseline (speedup 1.0000x reference)
#include <cuda_runtime.h>
#include <cuda_bf16.h>
#include <cstdint>

// Problem constants
#define B_      32
#define C_      3
#define H_      257
#define W_      257
#define STRIDE_ 4
#define NW_     61                 // windows per axis
#define WSZ_    289                // 17*17
#define PLANE_  (257*257)          // 66049
#define NWIN_   (B_*C_*NW_*NW_)    // 357216 windows total
#define SW_ELEMS  ((long long)NWIN_ * WSZ_)        // 103,235,424
#define S_ELEMS   ((long long)B_ * 12 * NW_ * NW_) // 1,428,864
#define S_OFF     SW_ELEMS
#define Q_OFF     (SW_ELEMS + S_ELEMS)             // 104,664,288

#define JT_       8                 // windows per block (along j)
#define NJT_      8                 // ceil(61/8)
#define TILE_COLS 45                // (JT_-1)*4 + 17
#define TILE_PAD  48                // padded row stride in smem
#define TILE_ROWS 17

// ---- Blackwell packed fp32 helpers (only add/mul/fma exist as f32x2 in PTX)
__device__ __forceinline__ uint64_t packf2(float a, float b) {
    uint64_t r; asm("mov.b64 %0, {%1, %2};" : "=l"(r) : "f"(a), "f"(b)); return r;
}
__device__ __forceinline__ void unpackf2(uint64_t p, float& a, float& b) {
    asm("mov.b64 {%0, %1}, %2;" : "=f"(a), "=f"(b) : "l"(p));
}
__device__ __forceinline__ uint64_t addf2(uint64_t a, uint64_t b) {
    uint64_t r; asm("add.rn.f32x2 %0, %1, %2;" : "=l"(r) : "l"(a), "l"(b)); return r;
}
__device__ __forceinline__ uint64_t mulf2(uint64_t a, uint64_t b) {
    uint64_t r; asm("mul.rn.f32x2 %0, %1, %2;" : "=l"(r) : "l"(a), "l"(b)); return r;
}
__device__ __forceinline__ uint64_t fmaf2(uint64_t a, uint64_t b, uint64_t c) {
    uint64_t r; asm("fma.rn.f32x2 %0, %1, %2, %3;" : "=l"(r) : "l"(a), "l"(b), "l"(c)); return r;
}

// Block = 8 adjacent windows along j (same bc, i). x tile (17 x 45) staged in
// smem with one coalesced pass; each warp then processes one window from smem
// and writes sw/q with phased float4 streaming stores. sum/sumsq/q-scaling use
// packed f32x2 arithmetic; min/max stay scalar (no packed form exists).
__global__ __launch_bounds__(256) void leafnet_fused_kernel(
    const float* __restrict__ x, float* __restrict__ out)
{
    __shared__ float tile[TILE_ROWS * TILE_PAD];

    // blockIdx.x -> (bc, i, jt)
    const int jt   = blockIdx.x & 7;          // NJT_ = 8
    const int rest = blockIdx.x >> 3;
    const int i    = rest % NW_;
    const int bc   = rest / NW_;               // b*3 + c
    const int j0   = jt * JT_;

    // ---- Cooperative coalesced tile load: rows [4i, 4i+17), cols [4j0, 4j0+45)
    {
        const float* xrow = x + (size_t)bc * PLANE_ + (size_t)(i * STRIDE_) * W_;
        const int cbase = j0 * STRIDE_;
        #pragma unroll
        for (int p = 0; p < 3; p++) {
            const int idx = threadIdx.x + p * 256;     // 765 valid
            if (idx < TILE_ROWS * TILE_COLS) {
                const int u = idx / TILE_COLS;
                const int c = idx - u * TILE_COLS;
                const int gc = cbase + c;
                tile[u * TILE_PAD + c] = (gc < W_) ? __ldg(xrow + u * W_ + gc) : 0.0f;
            }
        }
    }
    __syncthreads();

    const int w    = threadIdx.x >> 5;          // window slot in tile (0..7)
    const int lane = threadIdx.x & 31;
    const int j    = j0 + w;
    if (j >= NW_) return;                       // only last jt loses warps 5..7

    const int wid = (bc * NW_ + i) * NW_ + j;
    const float* wsm = tile + w * STRIDE_;      // + u*TILE_PAD + v
    float* swp = out + (size_t)wid * WSZ_;
    float* qp  = out + (size_t)Q_OFF + (size_t)wid * WSZ_;

    const int a         = (-wid) & 3;           // head count to reach 16B alignment
    const int ngroups   = (WSZ_ - a) >> 2;      // 71 or 72 float4 groups
    const int tailstart = a + (ngroups << 2);
    const int tail      = WSZ_ - tailstart;     // 0..3

    // Packed accumulators (2 lanes each) + scalar ones for head/tail & min/max
    uint64_t sum2 = packf2(0.0f, 0.0f);
    uint64_t sq2  = sum2;
    const uint64_t c64 = packf2(64.0f, 64.0f);
    float sum_s = 0.0f, sq_s = 0.0f, min_s = 1e30f, max_s = -1e30f;

    auto doScalar = [&](int e) {
        const int u = (e * 241) >> 12;          // e / 17 (exact for 0<=e<=288)
        const int v = e - u * 17;
        const float val = wsm[u * TILE_PAD + v];
        __stcs(swp + e, val);
        __stcs(qp  + e, floorf(val * 64.0f));   // digitize(linspace(0,1,65)) - 1
        sum_s += val;
        sq_s   = fmaf(val, val, sq_s);
        min_s  = fminf(min_s, val);
        max_s  = fmaxf(max_s, val);
    };

    auto doGroup = [&](int e0) {                // e0 16B-aligned within out
        float wv[4];
        #pragma unroll
        for (int tt = 0; tt < 4; tt++) {
            const int e = e0 + tt;
            const int u = (e * 241) >> 12;
            const int v = e - u * 17;
            wv[tt] = wsm[u * TILE_PAD + v];
        }
        const uint64_t p01 = packf2(wv[0], wv[1]);
        const uint64_t p23 = packf2(wv[2], wv[3]);
        sum2 = addf2(sum2, p01);  sum2 = addf2(sum2, p23);
        sq2  = fmaf2(p01, p01, sq2);  sq2 = fmaf2(p23, p23, sq2);
        min_s = fminf(min_s, fminf(fminf(wv[0], wv[1]), fminf(wv[2], wv[3])));
        max_s = fmaxf(max_s, fmaxf(fmaxf(wv[0], wv[1]), fmaxf(wv[2], wv[3])));
        // q = floor(v*64): packed multiply, scalar floor
        float s0, s1, s2, s3;
        unpackf2(mulf2(p01, c64), s0, s1);
        unpackf2(mulf2(p23, c64), s2, s3);
        __stcs(reinterpret_cast<float4*>(swp + e0),
               make_float4(wv[0], wv[1], wv[2], wv[3]));
        __stcs(reinterpret_cast<float4*>(qp + e0),
               make_float4(floorf(s0), floorf(s1), floorf(s2), floorf(s3)));
    };

    if (lane < a) doScalar(lane);
    doGroup(a + 4 * lane);                      // lane      < 71 <= ngroups : always
    doGroup(a + 4 * (lane + 32));               // lane + 32 < 64 < 71      : always
    if (lane + 64 < ngroups) doGroup(a + 4 * (lane + 64));   // 7-8 lanes
    if (lane < tail) doScalar(tailstart + lane);

    // Merge packed halves into scalar accumulators
    {
        float a0, a1;
        unpackf2(sum2, a0, a1);  sum_s += a0 + a1;
        unpackf2(sq2,  a0, a1);  sq_s  += a0 + a1;
    }

    // Warp reduction (butterfly)
    #pragma unroll
    for (int o = 16; o > 0; o >>= 1) {
        sum_s += __shfl_xor_sync(0xFFFFFFFFu, sum_s, o);
        sq_s  += __shfl_xor_sync(0xFFFFFFFFu, sq_s,  o);
        min_s  = fminf(min_s, __shfl_xor_sync(0xFFFFFFFFu, min_s, o));
        max_s  = fmaxf(max_s, __shfl_xor_sync(0xFFFFFFFFu, max_s, o));
    }

    if (lane == 0) {
        const float inv  = 1.0f / 289.0f;
        const float mean = sum_s * inv;
        const float var  = fmaxf(sq_s * inv - mean * mean, 0.0f);
        const float stdv = sqrtf(var);

        const int b = bc / 3;
        const int c = bc - b * 3;
        const int pos = i * NW_ + j;
        float* sp = out + (size_t)S_OFF + (size_t)b * 12 * (NW_ * NW_);
        // channel layout: [ (max-0.5)*4 | std*4 | (max-mean)*4 | (mean-min)*4 ] x C
        sp[(0 * 3 + c) * (NW_ * NW_) + pos] = (max_s - 0.5f) * 4.0f;
        sp[(1 * 3 + c) * (NW_ * NW_) + pos] = stdv * 4.0f;
        sp[(2 * 3 + c) * (NW_ * NW_) + pos] = (max_s - mean) * 4.0f;
        sp[(3 * 3 + c) * (NW_ * NW_) + pos] = (mean - min_s) * 4.0f;
    }
}

extern "C" void kernel_launch(void* const* d_in, const int* in_sizes, int n_in,
                              void* d_out, int out_size)
{
    const float* x = (const float*)d_in[0];   // (32,3,257,257) float32
    // d_in[1] = bins (65 floats) — uniform linspace(0,1,65); digitize-1 == floor(v*64)
    float* out = (float*)d_out;

    const int threads = 256;                  // 8 warps = 8 windows / block
    const int blocks  = (B_ * C_) * NW_ * NJT_;  // 96 * 61 * 8 = 46848
    leafnet_fused_kernel<<<blocks, threads>>>(x, out);
}

// round 8
// speedup vs baseline: 1.0867x; 1.0867x over previous
#include <cuda_runtime.h>
#include <cuda_bf16.h>
#include <cstdint>

// Problem constants
#define B_      32
#define C_      3
#define H_      257
#define W_      257
#define STRIDE_ 4
#define NW_     61                 // windows per axis
#define WSZ_    289                // 17*17
#define PLANE_  (257*257)          // 66049
#define NWIN_   (B_*C_*NW_*NW_)    // 357216 windows total
#define SW_ELEMS  ((long long)NWIN_ * WSZ_)        // 103,235,424
#define S_ELEMS   ((long long)B_ * 12 * NW_ * NW_) // 1,428,864
#define S_OFF     SW_ELEMS
#define Q_OFF     (SW_ELEMS + S_ELEMS)             // 104,664,288

#define JT_       8                 // windows per block (along j)
#define NJT_      8                 // ceil(61/8)
#define TILE_COLS 45                // (JT_-1)*4 + 17
#define TILE_PAD  48                // padded row stride in smem
#define TILE_ROWS 17

// ============================================================================
// Kernel 1: separable window stats -> s (tiny: 5.7 MB out).
// Block per (bc, i). Phase 1: per-column vertical aggregates over the 17 rows.
// Phase 2: thread j combines 17 columns -> window stats -> 4 s channels.
// ============================================================================
__global__ __launch_bounds__(256) void leafnet_stats_kernel(
    const float* __restrict__ x, float* __restrict__ out)
{
    __shared__ float vs[W_], vq[W_], vmn[W_], vmx[W_];

    const int i  = blockIdx.x % NW_;
    const int bc = blockIdx.x / NW_;           // b*3 + c
    const float* xp = x + (size_t)bc * PLANE_ + (size_t)(i * STRIDE_) * W_;

    for (int c = threadIdx.x; c < W_; c += 256) {
        float s = 0.0f, q = 0.0f, mn = 1e30f, mx = -1e30f;
        #pragma unroll
        for (int u = 0; u < 17; u++) {
            const float v = __ldg(xp + u * W_ + c);
            s += v; q = fmaf(v, v, q);
            mn = fminf(mn, v); mx = fmaxf(mx, v);
        }
        vs[c] = s; vq[c] = q; vmn[c] = mn; vmx[c] = mx;
    }
    __syncthreads();

    const int j = threadIdx.x;
    if (j < NW_) {
        float s = 0.0f, q = 0.0f, mn = 1e30f, mx = -1e30f;
        #pragma unroll
        for (int k = 0; k < 17; k++) {
            const int c = 4 * j + k;           // <= 256, in range
            s += vs[c]; q += vq[c];
            mn = fminf(mn, vmn[c]); mx = fmaxf(mx, vmx[c]);
        }
        const float inv  = 1.0f / 289.0f;
        const float mean = s * inv;
        const float var  = fmaxf(q * inv - mean * mean, 0.0f);
        const float stdv = sqrtf(var);

        const int b  = bc / 3;
        const int c0 = bc - b * 3;
        const int pos = i * NW_ + j;
        float* sp = out + (size_t)S_OFF + (size_t)b * 12 * (NW_ * NW_);
        // channel layout: [ (max-0.5)*4 | std*4 | (max-mean)*4 | (mean-min)*4 ] x C
        sp[(0 * 3 + c0) * (NW_ * NW_) + pos] = (mx - 0.5f) * 4.0f;
        sp[(1 * 3 + c0) * (NW_ * NW_) + pos] = stdv * 4.0f;
        sp[(2 * 3 + c0) * (NW_ * NW_) + pos] = (mx - mean) * 4.0f;
        sp[(3 * 3 + c0) * (NW_ * NW_) + pos] = (mean - mn) * 4.0f;
    }
}

// ============================================================================
// Kernel 2: lean gather-copy + quantize (the 826 MB sw/q streams).
// R3 structure with ALL stats machinery removed: smem tile, warp per window,
// phased float4 streaming stores. No reductions, no epilogue.
// ============================================================================
__global__ __launch_bounds__(256) void leafnet_copy_kernel(
    const float* __restrict__ x, float* __restrict__ out)
{
    __shared__ float tile[TILE_ROWS * TILE_PAD];

    // blockIdx.x -> (bc, i, jt)
    const int jt   = blockIdx.x & 7;           // NJT_ = 8
    const int rest = blockIdx.x >> 3;
    const int i    = rest % NW_;
    const int bc   = rest / NW_;               // b*3 + c
    const int j0   = jt * JT_;

    // ---- Cooperative coalesced tile load: rows [4i, 4i+17), cols [4j0, 4j0+45)
    {
        const float* xrow = x + (size_t)bc * PLANE_ + (size_t)(i * STRIDE_) * W_;
        const int cbase = j0 * STRIDE_;
        #pragma unroll
        for (int p = 0; p < 3; p++) {
            const int idx = threadIdx.x + p * 256;     // 765 valid
            if (idx < TILE_ROWS * TILE_COLS) {
                const int u = idx / TILE_COLS;
                const int c = idx - u * TILE_COLS;
                const int gc = cbase + c;
                tile[u * TILE_PAD + c] = (gc < W_) ? __ldg(xrow + u * W_ + gc) : 0.0f;
            }
        }
    }
    __syncthreads();

    const int w    = threadIdx.x >> 5;          // window slot in tile (0..7)
    const int lane = threadIdx.x & 31;
    const int j    = j0 + w;
    if (j >= NW_) return;                       // only last jt loses warps 5..7

    const int wid = (bc * NW_ + i) * NW_ + j;
    const float* wsm = tile + w * STRIDE_;      // + u*TILE_PAD + v
    float* swp = out + (size_t)wid * WSZ_;
    float* qp  = out + (size_t)Q_OFF + (size_t)wid * WSZ_;

    const int a         = (-wid) & 3;           // head count to reach 16B alignment
    const int ngroups   = (WSZ_ - a) >> 2;      // 71 or 72 float4 groups
    const int tailstart = a + (ngroups << 2);
    const int tail      = WSZ_ - tailstart;     // 0..3

    auto doScalar = [&](int e) {
        const int u = (e * 241) >> 12;          // e / 17 (exact for 0<=e<=288)
        const int v = e - u * 17;
        const float val = wsm[u * TILE_PAD + v];
        __stcs(swp + e, val);
        __stcs(qp  + e, floorf(val * 64.0f));   // digitize(linspace(0,1,65)) - 1
    };

    auto doGroup = [&](int e0) {                // e0 16B-aligned within out
        float wv[4];
        #pragma unroll
        for (int tt = 0; tt < 4; tt++) {
            const int e = e0 + tt;
            const int u = (e * 241) >> 12;
            const int v = e - u * 17;
            wv[tt] = wsm[u * TILE_PAD + v];
        }
        __stcs(reinterpret_cast<float4*>(swp + e0),
               make_float4(wv[0], wv[1], wv[2], wv[3]));
        __stcs(reinterpret_cast<float4*>(qp + e0),
               make_float4(floorf(wv[0] * 64.0f), floorf(wv[1] * 64.0f),
                           floorf(wv[2] * 64.0f), floorf(wv[3] * 64.0f)));
    };

    if (lane < a) doScalar(lane);
    doGroup(a + 4 * lane);                      // lane      < 71 <= ngroups : always
    doGroup(a + 4 * (lane + 32));               // lane + 32 < 64 < 71      : always
    if (lane + 64 < ngroups) doGroup(a + 4 * (lane + 64));   // 7-8 lanes
    if (lane < tail) doScalar(tailstart + lane);
}

extern "C" void kernel_launch(void* const* d_in, const int* in_sizes, int n_in,
                              void* d_out, int out_size)
{
    const float* x = (const float*)d_in[0];   // (32,3,257,257) float32
    // d_in[1] = bins (65 floats) — uniform linspace(0,1,65); digitize-1 == floor(v*64)
    float* out = (float*)d_out;

    // Stats kernel: one block per (bc, i)
    leafnet_stats_kernel<<<(B_ * C_) * NW_, 256>>>(x, out);
    // Copy/quantize kernel: 8 windows per block
    leafnet_copy_kernel<<<(B_ * C_) * NW_ * NJT_, 256>>>(x, out);
}

// round 9
// speedup vs baseline: 1.1388x; 1.0479x over previous
#include <cuda_runtime.h>
#include <cuda_bf16.h>
#include <cstdint>

// Problem constants
#define B_      32
#define C_      3
#define H_      257
#define W_      257
#define STRIDE_ 4
#define NW_     61                 // windows per axis
#define WSZ_    289                // 17*17
#define PLANE_  (257*257)          // 66049
#define NWIN_   (B_*C_*NW_*NW_)    // 357216 windows total
#define SW_ELEMS  ((long long)NWIN_ * WSZ_)        // 103,235,424
#define S_ELEMS   ((long long)B_ * 12 * NW_ * NW_) // 1,428,864
#define S_OFF     SW_ELEMS
#define Q_OFF     (SW_ELEMS + S_ELEMS)             // 104,664,288

#define JT_       8                 // windows per copy block (along j)
#define NJT_      8                 // ceil(61/8)
#define TILE_COLS 45                // (JT_-1)*4 + 17
#define TILE_PAD  48                // padded row stride in smem
#define TILE_ROWS 17

// One kernel, two block roles, interleaved 8:1 so stats blocks co-reside with
// copy blocks on every SM (stats ALU work hides in the copy stream's idle
// issue slots). Group of 9 blocks shares one (bc, i): 8 copy j-tiles + 1 stats.
__global__ __launch_bounds__(256, 8) void leafnet_kernel(
    const float* __restrict__ x, float* __restrict__ out)
{
    __shared__ float sbuf[4 * W_];             // stats: 4x257; copy uses 17*48=816

    const int grp = blockIdx.x / 9;
    const int sl  = blockIdx.x - grp * 9;      // 0..7 copy, 8 stats
    const int i   = grp % NW_;
    const int bc  = grp / NW_;                 // b*3 + c
    const float* xrow = x + (size_t)bc * PLANE_ + (size_t)(i * STRIDE_) * W_;

    if (sl == 8) {
        // ================= Stats role: separable window stats -> s ==========
        float* vs  = sbuf;
        float* vq  = sbuf + W_;
        float* vmn = sbuf + 2 * W_;
        float* vmx = sbuf + 3 * W_;

        for (int c = threadIdx.x; c < W_; c += 256) {
            float s = 0.0f, q = 0.0f, mn = 1e30f, mx = -1e30f;
            #pragma unroll
            for (int u = 0; u < 17; u++) {
                const float v = __ldg(xrow + u * W_ + c);
                s += v; q = fmaf(v, v, q);
                mn = fminf(mn, v); mx = fmaxf(mx, v);
            }
            vs[c] = s; vq[c] = q; vmn[c] = mn; vmx[c] = mx;
        }
        __syncthreads();

        const int j = threadIdx.x;
        if (j < NW_) {
            float s = 0.0f, q = 0.0f, mn = 1e30f, mx = -1e30f;
            #pragma unroll
            for (int k = 0; k < 17; k++) {
                const int c = 4 * j + k;
                s += vs[c]; q += vq[c];
                mn = fminf(mn, vmn[c]); mx = fmaxf(mx, vmx[c]);
            }
            const float inv  = 1.0f / 289.0f;
            const float mean = s * inv;
            const float var  = fmaxf(q * inv - mean * mean, 0.0f);
            const float stdv = sqrtf(var);

            const int b  = bc / 3;
            const int c0 = bc - b * 3;
            const int pos = i * NW_ + j;
            float* sp = out + (size_t)S_OFF + (size_t)b * 12 * (NW_ * NW_);
            // layout: [ (max-0.5)*4 | std*4 | (max-mean)*4 | (mean-min)*4 ] x C
            sp[(0 * 3 + c0) * (NW_ * NW_) + pos] = (mx - 0.5f) * 4.0f;
            sp[(1 * 3 + c0) * (NW_ * NW_) + pos] = stdv * 4.0f;
            sp[(2 * 3 + c0) * (NW_ * NW_) + pos] = (mx - mean) * 4.0f;
            sp[(3 * 3 + c0) * (NW_ * NW_) + pos] = (mean - mn) * 4.0f;
        }
        return;
    }

    // ================= Copy role: gather-copy + quantize =====================
    float* tile = sbuf;                        // 17 x TILE_PAD
    const int jt = sl;
    const int j0 = jt * JT_;

    {   // Cooperative coalesced tile load: rows [4i,4i+17), cols [4j0,4j0+45)
        const int cbase = j0 * STRIDE_;
        #pragma unroll
        for (int p = 0; p < 3; p++) {
            const int idx = threadIdx.x + p * 256;   // 765 valid
            if (idx < TILE_ROWS * TILE_COLS) {
                const int u = idx / TILE_COLS;
                const int c = idx - u * TILE_COLS;
                const int gc = cbase + c;
                tile[u * TILE_PAD + c] = (gc < W_) ? __ldg(xrow + u * W_ + gc) : 0.0f;
            }
        }
    }
    __syncthreads();

    const int w    = threadIdx.x >> 5;          // window slot (0..7)
    const int lane = threadIdx.x & 31;
    const int j    = j0 + w;
    if (j >= NW_) return;                       // only last jt loses warps 5..7

    const int wid = (bc * NW_ + i) * NW_ + j;
    const float* wsm = tile + w * STRIDE_;      // + u*TILE_PAD + v
    float* swp = out + (size_t)wid * WSZ_;
    float* qp  = out + (size_t)Q_OFF + (size_t)wid * WSZ_;

    const int a         = (-wid) & 3;           // head count to reach 16B alignment
    const int ngroups   = (WSZ_ - a) >> 2;      // 71 or 72 float4 groups
    const int tailstart = a + (ngroups << 2);
    const int tail      = WSZ_ - tailstart;     // 0..3

    auto doScalar = [&](int e) {
        const int u = (e * 241) >> 12;          // e / 17 (exact for 0<=e<=288)
        const int v = e - u * 17;
        const float val = wsm[u * TILE_PAD + v];
        __stcs(swp + e, val);
        __stcs(qp  + e, floorf(val * 64.0f));   // digitize(linspace(0,1,65)) - 1
    };

    auto doGroup = [&](int e0) {                // e0 16B-aligned within out
        float wv[4];
        #pragma unroll
        for (int tt = 0; tt < 4; tt++) {
            const int e = e0 + tt;
            const int u = (e * 241) >> 12;
            const int v = e - u * 17;
            wv[tt] = wsm[u * TILE_PAD + v];
        }
        __stcs(reinterpret_cast<float4*>(swp + e0),
               make_float4(wv[0], wv[1], wv[2], wv[3]));
        __stcs(reinterpret_cast<float4*>(qp + e0),
               make_float4(floorf(wv[0] * 64.0f), floorf(wv[1] * 64.0f),
                           floorf(wv[2] * 64.0f), floorf(wv[3] * 64.0f)));
    };

    if (lane < a) doScalar(lane);
    doGroup(a + 4 * lane);                      // lane      < 71 <= ngroups : always
    doGroup(a + 4 * (lane + 32));               // lane + 32 < 64 < 71      : always
    if (lane + 64 < ngroups) doGroup(a + 4 * (lane + 64));   // 7-8 lanes
    if (lane < tail) doScalar(tailstart + lane);
}

extern "C" void kernel_launch(void* const* d_in, const int* in_sizes, int n_in,
                              void* d_out, int out_size)
{
    const float* x = (const float*)d_in[0];   // (32,3,257,257) float32
    // d_in[1] = bins (65 floats) — uniform linspace(0,1,65); digitize-1 == floor(v*64)
    float* out = (float*)d_out;

    // 9 blocks per (bc, i): 8 copy j-tiles + 1 stats, interleaved for overlap
    const int blocks = (B_ * C_) * NW_ * 9;    // 96 * 61 * 9 = 52704
    leafnet_kernel<<<blocks, 256>>>(x, out);
}

// round 10
// speedup vs baseline: 1.1831x; 1.0389x over previous
#include <cuda_runtime.h>
#include <cuda_bf16.h>
#include <cstdint>

// Problem constants
#define B_      32
#define C_      3
#define H_      257
#define W_      257
#define STRIDE_ 4
#define NW_     61                 // windows per axis
#define WSZ_    289                // 17*17
#define PLANE_  (257*257)          // 66049
#define SW_ELEMS  ((long long)357216 * WSZ_)       // 103,235,424
#define S_ELEMS   ((long long)B_ * 12 * NW_ * NW_) // 1,428,864
#define S_OFF     SW_ELEMS
#define Q_OFF     (SW_ELEMS + S_ELEMS)             // 104,664,288

#define JT_       8                 // windows per copy block (along j)
#define NIP_      31                // ceil(61/2) i-pairs
#define TILE_COLS 45                // (JT_-1)*4 + 17
#define TILE_PAD  48                // padded row stride in smem
#define TILE_ROWS 21                // covers i0 (rows 0..16) and i0+1 (rows 4..20)
#define TILE_N    (TILE_ROWS * TILE_COLS)  // 945

// One kernel, two block roles, interleaved 8:2 per (bc, i-pair).
// Copy block: 21x45 x-tile staged once, each warp runs the window body for
// (i0, j) then (i0+1, j) -> 16 windows/block, 38% less tile-load per window.
// Stats blocks (2 per group) compute separable window stats -> s.
__global__ __launch_bounds__(256, 8) void leafnet_kernel(
    const float* __restrict__ x, float* __restrict__ out)
{
    __shared__ float sbuf[4 * W_];             // stats: 4x257=1028; copy tile: 21*48=1008

    const int sl  = blockIdx.x % 10;           // 0..7 copy jt, 8..9 stats
    const int grp = blockIdx.x / 10;
    const int ip  = grp % NIP_;
    const int bc  = grp / NIP_;                // b*3 + c
    const int i0  = ip * 2;

    if (sl >= 8) {
        // ================= Stats role: separable window stats -> s ==========
        const int i = i0 + (sl - 8);
        if (i >= NW_) return;
        const float* xrow = x + (size_t)bc * PLANE_ + (size_t)(i * STRIDE_) * W_;
        float* vs  = sbuf;
        float* vq  = sbuf + W_;
        float* vmn = sbuf + 2 * W_;
        float* vmx = sbuf + 3 * W_;

        for (int c = threadIdx.x; c < W_; c += 256) {
            float s = 0.0f, q = 0.0f, mn = 1e30f, mx = -1e30f;
            #pragma unroll
            for (int u = 0; u < 17; u++) {
                const float v = __ldg(xrow + u * W_ + c);
                s += v; q = fmaf(v, v, q);
                mn = fminf(mn, v); mx = fmaxf(mx, v);
            }
            vs[c] = s; vq[c] = q; vmn[c] = mn; vmx[c] = mx;
        }
        __syncthreads();

        const int j = threadIdx.x;
        if (j < NW_) {
            float s = 0.0f, q = 0.0f, mn = 1e30f, mx = -1e30f;
            #pragma unroll
            for (int k = 0; k < 17; k++) {
                const int c = 4 * j + k;
                s += vs[c]; q += vq[c];
                mn = fminf(mn, vmn[c]); mx = fmaxf(mx, vmx[c]);
            }
            const float inv  = 1.0f / 289.0f;
            const float mean = s * inv;
            const float var  = fmaxf(q * inv - mean * mean, 0.0f);
            const float stdv = sqrtf(var);

            const int b  = bc / 3;
            const int c0 = bc - b * 3;
            const int pos = i * NW_ + j;
            float* sp = out + (size_t)S_OFF + (size_t)b * 12 * (NW_ * NW_);
            // layout: [ (max-0.5)*4 | std*4 | (max-mean)*4 | (mean-min)*4 ] x C
            sp[(0 * 3 + c0) * (NW_ * NW_) + pos] = (mx - 0.5f) * 4.0f;
            sp[(1 * 3 + c0) * (NW_ * NW_) + pos] = stdv * 4.0f;
            sp[(2 * 3 + c0) * (NW_ * NW_) + pos] = (mx - mean) * 4.0f;
            sp[(3 * 3 + c0) * (NW_ * NW_) + pos] = (mean - mn) * 4.0f;
        }
        return;
    }

    // ================= Copy role: gather-copy + quantize, 2 i's per block ====
    float* tile = sbuf;                        // 21 x TILE_PAD
    const int jt = sl;
    const int j0 = jt * JT_;

    {   // Cooperative coalesced tile load: rows [4i0, 4i0+21), cols [4j0, 4j0+45)
        const float* xbase = x + (size_t)bc * PLANE_ + (size_t)(i0 * STRIDE_) * W_;
        const int cbase = j0 * STRIDE_;
        const int rbase = i0 * STRIDE_;
        #pragma unroll
        for (int p = 0; p < 4; p++) {
            const int idx = threadIdx.x + p * 256;   // 945 valid
            if (idx < TILE_N) {
                const int r  = idx / TILE_COLS;
                const int c  = idx - r * TILE_COLS;
                const int gc = cbase + c;
                const bool ok = (rbase + r < H_) && (gc < W_);
                tile[r * TILE_PAD + c] = ok ? __ldg(xbase + r * W_ + gc) : 0.0f;
            }
        }
    }
    __syncthreads();

    const int w    = threadIdx.x >> 5;          // window slot (0..7)
    const int lane = threadIdx.x & 31;
    const int j    = j0 + w;
    if (j >= NW_) return;                       // only last jt loses warps 5..7

    #pragma unroll 1
    for (int ii = 0; ii < 2; ii++) {
        const int i = i0 + ii;
        if (i >= NW_) break;                    // i0=60 pair has no second i

        const int wid = (bc * NW_ + i) * NW_ + j;
        const float* wsm = tile + ii * STRIDE_ * TILE_PAD + w * STRIDE_;
        float* swp = out + (size_t)wid * WSZ_;
        float* qp  = out + (size_t)Q_OFF + (size_t)wid * WSZ_;

        const int a         = (-wid) & 3;       // head count to reach 16B alignment
        const int ngroups   = (WSZ_ - a) >> 2;  // 71 or 72 float4 groups
        const int tailstart = a + (ngroups << 2);
        const int tail      = WSZ_ - tailstart; // 0..3

        auto doScalar = [&](int e) {
            const int u = (e * 241) >> 12;      // e / 17 (exact for 0<=e<=288)
            const int v = e - u * 17;
            const float val = wsm[u * TILE_PAD + v];
            __stcs(swp + e, val);
            __stcs(qp  + e, floorf(val * 64.0f)); // digitize(linspace(0,1,65)) - 1
        };

        auto doGroup = [&](int e0) {            // e0 16B-aligned within out
            float wv[4];
            #pragma unroll
            for (int tt = 0; tt < 4; tt++) {
                const int e = e0 + tt;
                const int u = (e * 241) >> 12;
                const int v = e - u * 17;
                wv[tt] = wsm[u * TILE_PAD + v];
            }
            __stcs(reinterpret_cast<float4*>(swp + e0),
                   make_float4(wv[0], wv[1], wv[2], wv[3]));
            __stcs(reinterpret_cast<float4*>(qp + e0),
                   make_float4(floorf(wv[0] * 64.0f), floorf(wv[1] * 64.0f),
                               floorf(wv[2] * 64.0f), floorf(wv[3] * 64.0f)));
        };

        if (lane < a) doScalar(lane);
        doGroup(a + 4 * lane);                  // lane      < 71 <= ngroups : always
        doGroup(a + 4 * (lane + 32));           // lane + 32 < 64 < 71      : always
        if (lane + 64 < ngroups) doGroup(a + 4 * (lane + 64));   // 7-8 lanes
        if (lane < tail) doScalar(tailstart + lane);
    }
}

extern "C" void kernel_launch(void* const* d_in, const int* in_sizes, int n_in,
                              void* d_out, int out_size)
{
    const float* x = (const float*)d_in[0];   // (32,3,257,257) float32
    // d_in[1] = bins (65 floats) — uniform linspace(0,1,65); digitize-1 == floor(v*64)
    float* out = (float*)d_out;

    // 10 blocks per (bc, i-pair): 8 copy j-tiles (2 i's each) + 2 stats
    const int blocks = (B_ * C_) * NIP_ * 10;  // 96 * 31 * 10 = 29760
    leafnet_kernel<<<blocks, 256>>>(x, out);
}